// round 2
// baseline (speedup 1.0000x reference)
#include <cuda_runtime.h>

#define NN 20000
#define EE 320000
#define TT 16
#define FIN 9
#define HID 128
#define HEADS 8
#define D1 1024          // HEADS*HID
#define PBLK 160
#define PCH 125          // 160*125 = 20000

// ---------------- static device scratch (no allocations allowed) ----------------
__device__ int   g_is64;
__device__ int   g_cnt[NN];
__device__ int   g_rowptr[NN + 1];
__device__ int   g_cursor[NN];
__device__ int   g_col[EE];
__device__ float g_h1[(size_t)NN * D1];      // 80 MB
__device__ float g_als1[NN * HEADS];
__device__ float g_ald1[NN * HEADS];
__device__ float g_out1[(size_t)NN * D1];    // 80 MB
__device__ float g_h2[(size_t)NN * HID];
__device__ float g_als2[NN];
__device__ float g_ald2[NN];
__device__ float g_out2[(size_t)NN * HID];
__device__ float g_partial[PBLK * HID];
__device__ float g_emb[TT * HID];

// ---------------- dtype detection (int64 vs int32 edge_index) ----------------
__global__ void k_detect(const void* ei) {
    if (threadIdx.x == 0 && blockIdx.x == 0) {
        const long long* p = (const long long*)ei;
        int ok = 1;
        for (int i = 0; i < 8; i++) {
            long long v = p[i];
            if (v < 0 || v >= NN) ok = 0;
        }
        g_is64 = ok;
    }
}

__device__ __forceinline__ int edge_at(const void* ei, size_t idx, int is64) {
    return is64 ? (int)((const long long*)ei)[idx] : ((const int*)ei)[idx];
}

// ---------------- CSR construction ----------------
__global__ void k_zero_cnt() {
    int i = blockIdx.x * blockDim.x + threadIdx.x;
    if (i < NN) g_cnt[i] = 0;
}

__global__ void k_count(const void* __restrict__ ei) {
    int e = blockIdx.x * blockDim.x + threadIdx.x;
    if (e < EE) {
        int is64 = g_is64;
        int d = edge_at(ei, (size_t)EE + e, is64);
        if (d >= 0 && d < NN) atomicAdd(&g_cnt[d], 1);
    }
}

// single-block scan of 20000 counts -> rowptr
__global__ void k_scan() {
    __shared__ int part[1024];
    int tid = threadIdx.x;
    const int CH = (NN + 1023) / 1024;  // 20
    int base = tid * CH;
    int s = 0;
    for (int i = 0; i < CH; i++) {
        int idx = base + i;
        if (idx < NN) s += g_cnt[idx];
    }
    part[tid] = s;
    __syncthreads();
    // Hillis-Steele inclusive scan
    for (int off = 1; off < 1024; off <<= 1) {
        int v = (tid >= off) ? part[tid - off] : 0;
        __syncthreads();
        part[tid] += v;
        __syncthreads();
    }
    int run = part[tid] - s;  // exclusive prefix for this chunk
    for (int i = 0; i < CH; i++) {
        int idx = base + i;
        if (idx < NN) {
            g_rowptr[idx] = run;
            run += g_cnt[idx];
        }
    }
    if (tid == 1023) g_rowptr[NN] = part[1023];
}

__global__ void k_cursor() {
    int i = blockIdx.x * blockDim.x + threadIdx.x;
    if (i < NN) g_cursor[i] = g_rowptr[i];
}

__global__ void k_fill(const void* __restrict__ ei) {
    int e = blockIdx.x * blockDim.x + threadIdx.x;
    if (e < EE) {
        int is64 = g_is64;
        int s = edge_at(ei, (size_t)e, is64);
        int d = edge_at(ei, (size_t)EE + e, is64);
        if (s >= 0 && s < NN && d >= 0 && d < NN) {
            int p = atomicAdd(&g_cursor[d], 1);
            g_col[p] = s;
        }
    }
}

// ---------------- GAT1: linear + attention logits ----------------
// block = 128 threads, handles 64 nodes; W1 (9x1024 = 36KB) staged in shared.
__global__ void __launch_bounds__(128) k_gat1_lin(
    const float* __restrict__ x, const float* __restrict__ W1,
    const float* __restrict__ as1, const float* __restrict__ ad1) {
    __shared__ float sW[FIN * D1];
    __shared__ float sx[FIN];
    __shared__ float red[64];
    int tid = threadIdx.x;
    for (int i = tid; i < FIN * D1; i += 128) sW[i] = W1[i];
    float av[HEADS], dv[HEADS];
#pragma unroll
    for (int j = 0; j < HEADS; j++) {
        av[j] = as1[j * HID + tid];
        dv[j] = ad1[j * HID + tid];
    }
    __syncthreads();
    int n0 = blockIdx.x * 64;
    int lane = tid & 31, w = tid >> 5;
    for (int nn = 0; nn < 64; nn++) {
        int n = n0 + nn;
        if (n >= NN) break;
        if (tid < FIN) sx[tid] = x[(size_t)n * FIN + tid];
        __syncthreads();
        float xv[FIN];
#pragma unroll
        for (int k = 0; k < FIN; k++) xv[k] = sx[k];
        float hv[HEADS];
#pragma unroll
        for (int j = 0; j < HEADS; j++) {
            float hh = 0.f;
#pragma unroll
            for (int k = 0; k < FIN; k++) hh += xv[k] * sW[k * D1 + j * HID + tid];
            hv[j] = hh;
            g_h1[(size_t)n * D1 + j * HID + tid] = hh;
        }
#pragma unroll
        for (int j = 0; j < HEADS; j++) {
            float v1 = hv[j] * av[j];
            float v2 = hv[j] * dv[j];
            for (int o = 16; o; o >>= 1) {
                v1 += __shfl_down_sync(0xffffffffu, v1, o);
                v2 += __shfl_down_sync(0xffffffffu, v2, o);
            }
            if (lane == 0) { red[j * 4 + w] = v1; red[32 + j * 4 + w] = v2; }
        }
        __syncthreads();
        if (tid < 16) {
            int jj = tid & 7, which = tid >> 3;
            float s = red[which * 32 + jj * 4 + 0] + red[which * 32 + jj * 4 + 1] +
                      red[which * 32 + jj * 4 + 2] + red[which * 32 + jj * 4 + 3];
            if (which == 0) g_als1[n * HEADS + jj] = s;
            else            g_ald1[n * HEADS + jj] = s;
        }
        __syncthreads();
    }
}

// ---------------- GAT1: softmax + weighted aggregation (per dst node) ----------------
__global__ void __launch_bounds__(128) k_gat1_agg(const float* __restrict__ b1) {
    int n = blockIdx.x, tid = threadIdx.x;
    int start = g_rowptr[n], end = g_rowptr[n + 1];
    int deg = end - start + 1;          // + implicit self loop
    int j = tid & 7, ln = tid >> 3;     // 16 edge lanes x 8 heads
    float aldj = g_ald1[n * HEADS + j];
    __shared__ float sm[128];
    __shared__ float s_mx[8], s_inv[8];
    __shared__ float s_alpha[16 * 8];
    __shared__ int s_src[16];

    // pass 1: per-head max
    float mx = -1e30f;
    for (int i = ln; i < deg; i += 16) {
        int s = (i < deg - 1) ? g_col[start + i] : n;
        float l = g_als1[s * HEADS + j] + aldj;
        l = (l > 0.f) ? l : 0.2f * l;
        mx = fmaxf(mx, l);
    }
    sm[tid] = mx;
    __syncthreads();
    for (int st = 8; st > 0; st >>= 1) {
        if (ln < st) sm[tid] = fmaxf(sm[tid], sm[tid + st * 8]);
        __syncthreads();
    }
    if (tid < 8) s_mx[tid] = sm[tid];
    __syncthreads();
    float mj = s_mx[j];

    // pass 2: per-head sum of exp
    float sum = 0.f;
    for (int i = ln; i < deg; i += 16) {
        int s = (i < deg - 1) ? g_col[start + i] : n;
        float l = g_als1[s * HEADS + j] + aldj;
        l = (l > 0.f) ? l : 0.2f * l;
        sum += __expf(l - mj);
    }
    __syncthreads();
    sm[tid] = sum;
    __syncthreads();
    for (int st = 8; st > 0; st >>= 1) {
        if (ln < st) sm[tid] += sm[tid + st * 8];
        __syncthreads();
    }
    if (tid < 8) s_inv[tid] = 1.f / (sm[tid] + 1e-16f);
    __syncthreads();
    float invj = s_inv[j];

    // pass 3: weighted accumulation; thread = channel, 8 head-accumulators
    float acc[HEADS];
#pragma unroll
    for (int q = 0; q < HEADS; q++) acc[q] = 0.f;
    for (int base = 0; base < deg; base += 16) {
        int cnt = min(16, deg - base);
        __syncthreads();
        if (ln < cnt) {
            int i = base + ln;
            int s = (i < deg - 1) ? g_col[start + i] : n;
            float l = g_als1[s * HEADS + j] + aldj;
            l = (l > 0.f) ? l : 0.2f * l;
            s_alpha[ln * 8 + j] = __expf(l - mj) * invj;
            if (j == 0) s_src[ln] = s;
        }
        __syncthreads();
        for (int ii = 0; ii < cnt; ii++) {
            const float* hp = &g_h1[(size_t)s_src[ii] * D1 + tid];
#pragma unroll
            for (int q = 0; q < HEADS; q++) acc[q] += s_alpha[ii * 8 + q] * hp[q * HID];
        }
    }
#pragma unroll
    for (int q = 0; q < HEADS; q++) {
        float v = acc[q] + b1[q * HID + tid];
        g_out1[(size_t)n * D1 + q * HID + tid] = (v > 0.f) ? v : 0.f;
    }
}

// ---------------- GAT2 GEMM: h2[N,128] = out1[N,1024] @ W2[1024,128] ----------------
__global__ void __launch_bounds__(256) k_gemm2(const float* __restrict__ B) {
    __shared__ float As[16][128];
    __shared__ float Bs[16][128];
    int tid = threadIdx.x;
    int m0 = blockIdx.x * 128;
    int tx = tid & 15, ty = tid >> 4;
    int ar = tid >> 2;           // 0..63
    int ac = (tid & 3) * 4;      // 0,4,8,12
    int bk = tid >> 5;           // 0..7
    int bc = (tid & 31) * 4;
    float acc[8][8];
#pragma unroll
    for (int i = 0; i < 8; i++)
#pragma unroll
        for (int jj = 0; jj < 8; jj++) acc[i][jj] = 0.f;

    for (int k0 = 0; k0 < D1; k0 += 16) {
#pragma unroll
        for (int h = 0; h < 2; h++) {
            int r = ar + h * 64;
            int gr = m0 + r;
            float4 a = (gr < NN) ? *(const float4*)&g_out1[(size_t)gr * D1 + k0 + ac]
                                 : make_float4(0.f, 0.f, 0.f, 0.f);
            As[ac + 0][r] = a.x; As[ac + 1][r] = a.y;
            As[ac + 2][r] = a.z; As[ac + 3][r] = a.w;
        }
#pragma unroll
        for (int h = 0; h < 2; h++) {
            int k = bk + h * 8;
            *(float4*)&Bs[k][bc] = *(const float4*)&B[(size_t)(k0 + k) * HID + bc];
        }
        __syncthreads();
#pragma unroll
        for (int k = 0; k < 16; k++) {
            float a[8], bb[8];
            *(float4*)&a[0]  = *(float4*)&As[k][ty * 8];
            *(float4*)&a[4]  = *(float4*)&As[k][ty * 8 + 4];
            *(float4*)&bb[0] = *(float4*)&Bs[k][tx * 8];
            *(float4*)&bb[4] = *(float4*)&Bs[k][tx * 8 + 4];
#pragma unroll
            for (int i = 0; i < 8; i++)
#pragma unroll
                for (int jj = 0; jj < 8; jj++) acc[i][jj] += a[i] * bb[jj];
        }
        __syncthreads();
    }
#pragma unroll
    for (int i = 0; i < 8; i++) {
        int gr = m0 + ty * 8 + i;
        if (gr < NN) {
            *(float4*)&g_h2[(size_t)gr * HID + tx * 8] =
                make_float4(acc[i][0], acc[i][1], acc[i][2], acc[i][3]);
            *(float4*)&g_h2[(size_t)gr * HID + tx * 8 + 4] =
                make_float4(acc[i][4], acc[i][5], acc[i][6], acc[i][7]);
        }
    }
}

// ---------------- GAT2 attention logits ----------------
__global__ void __launch_bounds__(128) k_al2(const float* __restrict__ as2,
                                             const float* __restrict__ ad2) {
    int n = blockIdx.x, tid = threadIdx.x;
    float v = g_h2[(size_t)n * HID + tid];
    float ps = v * as2[tid], pd = v * ad2[tid];
    __shared__ float sh[8];
    int lane = tid & 31, w = tid >> 5;
    for (int o = 16; o; o >>= 1) {
        ps += __shfl_down_sync(0xffffffffu, ps, o);
        pd += __shfl_down_sync(0xffffffffu, pd, o);
    }
    if (lane == 0) { sh[w] = ps; sh[4 + w] = pd; }
    __syncthreads();
    if (tid == 0) g_als2[n] = sh[0] + sh[1] + sh[2] + sh[3];
    if (tid == 1) g_ald2[n] = sh[4] + sh[5] + sh[6] + sh[7];
}

// ---------------- GAT2: softmax + aggregation ----------------
__global__ void __launch_bounds__(128) k_gat2_agg(const float* __restrict__ b2) {
    int n = blockIdx.x, tid = threadIdx.x;
    int start = g_rowptr[n], end = g_rowptr[n + 1];
    int deg = end - start + 1;
    float aldn = g_ald2[n];
    __shared__ float sm[128];
    __shared__ float s_stat[2];
    __shared__ float s_alpha[128];
    __shared__ int s_src[128];

    float mx = -1e30f;
    for (int i = tid; i < deg; i += 128) {
        int s = (i < deg - 1) ? g_col[start + i] : n;
        float l = g_als2[s] + aldn;
        l = (l > 0.f) ? l : 0.2f * l;
        mx = fmaxf(mx, l);
    }
    sm[tid] = mx;
    __syncthreads();
    for (int st = 64; st > 0; st >>= 1) {
        if (tid < st) sm[tid] = fmaxf(sm[tid], sm[tid + st]);
        __syncthreads();
    }
    if (tid == 0) s_stat[0] = sm[0];
    __syncthreads();
    float m = s_stat[0];

    float sum = 0.f;
    for (int i = tid; i < deg; i += 128) {
        int s = (i < deg - 1) ? g_col[start + i] : n;
        float l = g_als2[s] + aldn;
        l = (l > 0.f) ? l : 0.2f * l;
        sum += __expf(l - m);
    }
    __syncthreads();
    sm[tid] = sum;
    __syncthreads();
    for (int st = 64; st > 0; st >>= 1) {
        if (tid < st) sm[tid] += sm[tid + st];
        __syncthreads();
    }
    if (tid == 0) s_stat[1] = 1.f / (sm[0] + 1e-16f);
    __syncthreads();
    float inv = s_stat[1];

    float acc = 0.f;
    for (int base = 0; base < deg; base += 128) {
        int cnt = min(128, deg - base);
        __syncthreads();
        if (tid < cnt) {
            int i = base + tid;
            int s = (i < deg - 1) ? g_col[start + i] : n;
            float l = g_als2[s] + aldn;
            l = (l > 0.f) ? l : 0.2f * l;
            s_alpha[tid] = __expf(l - m) * inv;
            s_src[tid] = s;
        }
        __syncthreads();
        for (int ii = 0; ii < cnt; ii++)
            acc += s_alpha[ii] * g_h2[(size_t)s_src[ii] * HID + tid];
    }
    float v = acc + b2[tid];
    g_out2[(size_t)n * HID + tid] = (v > 0.f) ? v : 0.f;
}

// ---------------- deterministic mean pool over nodes ----------------
__global__ void __launch_bounds__(128) k_pool_a() {
    int c = threadIdx.x, b = blockIdx.x;
    int n0 = b * PCH, n1 = min(n0 + PCH, NN);
    float s = 0.f;
    for (int n = n0; n < n1; n++) s += g_out2[(size_t)n * HID + c];
    g_partial[b * HID + c] = s;
}

__global__ void __launch_bounds__(128) k_pool_b(int t) {
    int c = threadIdx.x;
    float s = 0.f;
    for (int b = 0; b < PBLK; b++) s += g_partial[b * HID + c];
    g_emb[t * HID + c] = s * (1.0f / NN);
}

// ---------------- GRU + output head ----------------
__global__ void __launch_bounds__(128) k_gru(
    const float* __restrict__ wih, const float* __restrict__ whh,
    const float* __restrict__ bih, const float* __restrict__ bhh,
    const float* __restrict__ wout, const float* __restrict__ bout,
    float* __restrict__ out) {
    int tid = threadIdx.x;
    __shared__ float h[HID], xt[HID];
    __shared__ float red[4];
    h[tid] = 0.f;
    __syncthreads();
    for (int t = 0; t < TT; t++) {
        xt[tid] = g_emb[t * HID + tid];
        __syncthreads();
        float gi[3], gh[3];
#pragma unroll
        for (int q = 0; q < 3; q++) {
            int r = q * HID + tid;
            float s1 = bih[r], s2 = bhh[r];
            const float* wi = &wih[(size_t)r * HID];
            const float* wh = &whh[(size_t)r * HID];
            for (int c = 0; c < HID; c++) {
                s1 += xt[c] * wi[c];
                s2 += h[c] * wh[c];
            }
            gi[q] = s1;
            gh[q] = s2;
        }
        float r  = 1.f / (1.f + __expf(-(gi[0] + gh[0])));
        float z  = 1.f / (1.f + __expf(-(gi[1] + gh[1])));
        float nn = tanhf(gi[2] + r * gh[2]);
        float hn = (1.f - z) * nn + z * h[tid];
        __syncthreads();
        h[tid] = hn;
        __syncthreads();
        float v = hn * wout[tid];
        int lane = tid & 31, w = tid >> 5;
        for (int o = 16; o; o >>= 1) v += __shfl_down_sync(0xffffffffu, v, o);
        if (lane == 0) red[w] = v;
        __syncthreads();
        if (tid == 0) out[t] = red[0] + red[1] + red[2] + red[3] + bout[0];
        __syncthreads();
    }
}

// ---------------- launch ----------------
extern "C" void kernel_launch(void* const* d_in, const int* in_sizes, int n_in,
                              void* d_out, int out_size) {
    const float* x    = (const float*)d_in[0];
    const void*  ei   = d_in[1];
    const float* W1   = (const float*)d_in[2];
    const float* as1  = (const float*)d_in[3];
    const float* ad1  = (const float*)d_in[4];
    const float* b1   = (const float*)d_in[5];
    const float* W2   = (const float*)d_in[6];
    const float* as2  = (const float*)d_in[7];
    const float* ad2  = (const float*)d_in[8];
    const float* b2   = (const float*)d_in[9];
    const float* wih  = (const float*)d_in[10];
    const float* whh  = (const float*)d_in[11];
    const float* bih  = (const float*)d_in[12];
    const float* bhh  = (const float*)d_in[13];
    const float* wout = (const float*)d_in[14];
    const float* bout = (const float*)d_in[15];
    float* out = (float*)d_out;

    // CSR by dst (edge structure shared across all timesteps / both layers)
    k_detect<<<1, 32>>>(ei);
    k_zero_cnt<<<(NN + 255) / 256, 256>>>();
    k_count<<<(EE + 255) / 256, 256>>>(ei);
    k_scan<<<1, 1024>>>();
    k_cursor<<<(NN + 255) / 256, 256>>>();
    k_fill<<<(EE + 255) / 256, 256>>>(ei);

    for (int t = 0; t < TT; t++) {
        k_gat1_lin<<<(NN + 63) / 64, 128>>>(x + (size_t)t * NN * FIN, W1, as1, ad1);
        k_gat1_agg<<<NN, 128>>>(b1);
        k_gemm2<<<(NN + 127) / 128, 256>>>(W2);
        k_al2<<<NN, 128>>>(as2, ad2);
        k_gat2_agg<<<NN, 128>>>(b2);
        k_pool_a<<<PBLK, 128>>>();
        k_pool_b<<<1, 128>>>(t);
    }
    k_gru<<<1, 128>>>(wih, whh, bih, bhh, wout, bout, out);
}

// round 3
// speedup vs baseline: 1.7099x; 1.7099x over previous
#include <cuda_runtime.h>
#include <cuda_fp16.h>

#define NN 20000
#define EE 320000
#define TT 16
#define FIN 9
#define HID 128
#define HEADS 8
#define D1 1024          // HEADS*HID
#define PBLK 160
#define PCH 125          // 160*125 = 20000

// ---------------- static device scratch ----------------
__device__ int   g_is64;
__device__ int   g_cnt[NN];
__device__ int   g_rowptr[NN + 1];
__device__ int   g_cursor[NN];
__device__ int   g_col[EE];
__device__ __align__(16) __half g_h1[(size_t)NN * D1];     // 40 MB (fp16)
__device__ float g_als1[NN * HEADS];
__device__ float g_ald1[NN * HEADS];
__device__ __align__(16) __half g_out1[(size_t)NN * D1];   // 40 MB (fp16) = GEMM A
__device__ __align__(16) __half g_W2h[D1 * HID];           // fp16 W2
__device__ __align__(16) __half g_h2[(size_t)NN * HID];    // fp16
__device__ float g_als2[NN];
__device__ float g_ald2[NN];
__device__ float g_out2[(size_t)NN * HID];
__device__ float g_partial[PBLK * HID];
__device__ float g_emb[TT * HID];

__device__ __forceinline__ int edge_at(const void* ei, size_t idx, int is64) {
    return is64 ? (int)((const long long*)ei)[idx] : ((const int*)ei)[idx];
}

// ---------------- setup: detect dtype + zero counts ----------------
__global__ void k_init(const void* ei) {
    int i = blockIdx.x * blockDim.x + threadIdx.x;
    if (i == 0) {
        const long long* p = (const long long*)ei;
        int ok = 1;
        for (int q = 0; q < 8; q++) {
            long long v = p[q];
            if (v < 0 || v >= NN) ok = 0;
        }
        g_is64 = ok;
    }
    if (i < NN) g_cnt[i] = 0;
}

__global__ void k_count(const void* __restrict__ ei) {
    int e = blockIdx.x * blockDim.x + threadIdx.x;
    if (e < EE) {
        int d = edge_at(ei, (size_t)EE + e, g_is64);
        if (d >= 0 && d < NN) atomicAdd(&g_cnt[d], 1);
    }
}

// single-block scan of counts -> rowptr (+ cursor init)
__global__ void k_scan() {
    __shared__ int part[1024];
    int tid = threadIdx.x;
    const int CH = (NN + 1023) / 1024;  // 20
    int base = tid * CH;
    int s = 0;
    for (int i = 0; i < CH; i++) {
        int idx = base + i;
        if (idx < NN) s += g_cnt[idx];
    }
    part[tid] = s;
    __syncthreads();
    for (int off = 1; off < 1024; off <<= 1) {
        int v = (tid >= off) ? part[tid - off] : 0;
        __syncthreads();
        part[tid] += v;
        __syncthreads();
    }
    int run = part[tid] - s;
    for (int i = 0; i < CH; i++) {
        int idx = base + i;
        if (idx < NN) {
            g_rowptr[idx] = run;
            g_cursor[idx] = run;
            run += g_cnt[idx];
        }
    }
    if (tid == 1023) g_rowptr[NN] = part[1023];
}

__global__ void k_fill(const void* __restrict__ ei) {
    int e = blockIdx.x * blockDim.x + threadIdx.x;
    if (e < EE) {
        int is64 = g_is64;
        int s = edge_at(ei, (size_t)e, is64);
        int d = edge_at(ei, (size_t)EE + e, is64);
        if (s >= 0 && s < NN && d >= 0 && d < NN) {
            int p = atomicAdd(&g_cursor[d], 1);
            g_col[p] = s;
        }
    }
}

__global__ void k_w2h(const float* __restrict__ W2) {
    int i = blockIdx.x * blockDim.x + threadIdx.x;
    if (i < D1 * HID) g_W2h[i] = __float2half(W2[i]);
}

// ---------------- GAT1: linear + attention logits ----------------
__global__ void __launch_bounds__(128) k_gat1_lin(
    const float* __restrict__ x, const float* __restrict__ W1,
    const float* __restrict__ as1, const float* __restrict__ ad1) {
    __shared__ float sW[FIN * D1];
    __shared__ float sx[FIN];
    __shared__ float red[64];
    int tid = threadIdx.x;
    for (int i = tid; i < FIN * D1; i += 128) sW[i] = W1[i];
    float av[HEADS], dv[HEADS];
#pragma unroll
    for (int j = 0; j < HEADS; j++) {
        av[j] = as1[j * HID + tid];
        dv[j] = ad1[j * HID + tid];
    }
    __syncthreads();
    int n0 = blockIdx.x * 64;
    int lane = tid & 31, w = tid >> 5;
    for (int nn = 0; nn < 64; nn++) {
        int n = n0 + nn;
        if (n >= NN) break;
        if (tid < FIN) sx[tid] = x[(size_t)n * FIN + tid];
        __syncthreads();
        float xv[FIN];
#pragma unroll
        for (int k = 0; k < FIN; k++) xv[k] = sx[k];
        float hv[HEADS];
#pragma unroll
        for (int j = 0; j < HEADS; j++) {
            float hh = 0.f;
#pragma unroll
            for (int k = 0; k < FIN; k++) hh += xv[k] * sW[k * D1 + j * HID + tid];
            hv[j] = hh;
            g_h1[(size_t)n * D1 + j * HID + tid] = __float2half(hh);
        }
#pragma unroll
        for (int j = 0; j < HEADS; j++) {
            float v1 = hv[j] * av[j];
            float v2 = hv[j] * dv[j];
            for (int o = 16; o; o >>= 1) {
                v1 += __shfl_down_sync(0xffffffffu, v1, o);
                v2 += __shfl_down_sync(0xffffffffu, v2, o);
            }
            if (lane == 0) { red[j * 4 + w] = v1; red[32 + j * 4 + w] = v2; }
        }
        __syncthreads();
        if (tid < 16) {
            int jj = tid & 7, which = tid >> 3;
            float s = red[which * 32 + jj * 4 + 0] + red[which * 32 + jj * 4 + 1] +
                      red[which * 32 + jj * 4 + 2] + red[which * 32 + jj * 4 + 3];
            if (which == 0) g_als1[n * HEADS + jj] = s;
            else            g_ald1[n * HEADS + jj] = s;
        }
        __syncthreads();
    }
}

// ---------------- GAT1: softmax + aggregation ----------------
// thread t handles 8 consecutive channels (one uint4 of halfs), all same head (t>>4)
__global__ void __launch_bounds__(128) k_gat1_agg(const float* __restrict__ b1) {
    int n = blockIdx.x, tid = threadIdx.x;
    int start = g_rowptr[n], end = g_rowptr[n + 1];
    int deg = end - start + 1;          // + self loop
    int j8 = tid & 7, ln = tid >> 3;    // softmax mapping: 16 lanes x 8 heads
    float aldj = g_ald1[n * HEADS + j8];
    __shared__ float sm[128];
    __shared__ float s_mx[8], s_inv[8];
    __shared__ float s_alpha[16 * 8];
    __shared__ int s_src[16];

    // pass 1: per-head max
    float mx = -1e30f;
    for (int i = ln; i < deg; i += 16) {
        int s = (i < deg - 1) ? g_col[start + i] : n;
        float l = g_als1[s * HEADS + j8] + aldj;
        l = (l > 0.f) ? l : 0.2f * l;
        mx = fmaxf(mx, l);
    }
    sm[tid] = mx;
    __syncthreads();
    for (int st = 8; st > 0; st >>= 1) {
        if (ln < st) sm[tid] = fmaxf(sm[tid], sm[tid + st * 8]);
        __syncthreads();
    }
    if (tid < 8) s_mx[tid] = sm[tid];
    __syncthreads();
    float mj = s_mx[j8];

    // pass 2: per-head sum of exp
    float sum = 0.f;
    for (int i = ln; i < deg; i += 16) {
        int s = (i < deg - 1) ? g_col[start + i] : n;
        float l = g_als1[s * HEADS + j8] + aldj;
        l = (l > 0.f) ? l : 0.2f * l;
        sum += __expf(l - mj);
    }
    __syncthreads();
    sm[tid] = sum;
    __syncthreads();
    for (int st = 8; st > 0; st >>= 1) {
        if (ln < st) sm[tid] += sm[tid + st * 8];
        __syncthreads();
    }
    if (tid < 8) s_inv[tid] = 1.f / (sm[tid] + 1e-16f);
    __syncthreads();
    float invj = s_inv[j8];

    // pass 3: vectorized weighted accumulation
    int jh = tid >> 4;                  // head for channels 8t..8t+7
    float acc[8];
#pragma unroll
    for (int q = 0; q < 8; q++) acc[q] = 0.f;
    for (int base = 0; base < deg; base += 16) {
        int cnt = min(16, deg - base);
        __syncthreads();
        if (ln < cnt) {
            int i = base + ln;
            int s = (i < deg - 1) ? g_col[start + i] : n;
            float l = g_als1[s * HEADS + j8] + aldj;
            l = (l > 0.f) ? l : 0.2f * l;
            s_alpha[ln * 8 + j8] = __expf(l - mj) * invj;
            if (j8 == 0) s_src[ln] = s;
        }
        __syncthreads();
        for (int ii = 0; ii < cnt; ii++) {
            float a = s_alpha[ii * 8 + jh];
            uint4 v = *(const uint4*)&g_h1[(size_t)s_src[ii] * D1 + tid * 8];
            float2 f0 = __half22float2(*(__half2*)&v.x);
            float2 f1 = __half22float2(*(__half2*)&v.y);
            float2 f2 = __half22float2(*(__half2*)&v.z);
            float2 f3 = __half22float2(*(__half2*)&v.w);
            acc[0] += a * f0.x; acc[1] += a * f0.y;
            acc[2] += a * f1.x; acc[3] += a * f1.y;
            acc[4] += a * f2.x; acc[5] += a * f2.y;
            acc[6] += a * f3.x; acc[7] += a * f3.y;
        }
    }
    float4 bA = *(const float4*)&b1[tid * 8];
    float4 bB = *(const float4*)&b1[tid * 8 + 4];
    float r0 = fmaxf(acc[0] + bA.x, 0.f), r1 = fmaxf(acc[1] + bA.y, 0.f);
    float r2 = fmaxf(acc[2] + bA.z, 0.f), r3 = fmaxf(acc[3] + bA.w, 0.f);
    float r4 = fmaxf(acc[4] + bB.x, 0.f), r5 = fmaxf(acc[5] + bB.y, 0.f);
    float r6 = fmaxf(acc[6] + bB.z, 0.f), r7 = fmaxf(acc[7] + bB.w, 0.f);
    __half2 p0 = __floats2half2_rn(r0, r1);
    __half2 p1 = __floats2half2_rn(r2, r3);
    __half2 p2 = __floats2half2_rn(r4, r5);
    __half2 p3 = __floats2half2_rn(r6, r7);
    uint4 o;
    o.x = *(unsigned*)&p0; o.y = *(unsigned*)&p1;
    o.z = *(unsigned*)&p2; o.w = *(unsigned*)&p3;
    *(uint4*)&g_out1[(size_t)n * D1 + tid * 8] = o;
}

// ---------------- tensor-core GEMM: h2[N,128] = out1[N,1024] @ W2h ----------------
// BM=128, BN=128, BK=32; 256 threads = 8 warps (4 m x 2 n), warp tile 32x64
__device__ __forceinline__ int aswz(int row, int col) {   // As stride 64 halfs
    int chunk = col >> 3;
    int sw = chunk ^ (row & 7);
    return row * 64 + sw * 8 + (col & 7);
}
__device__ __forceinline__ int bswz(int row, int col) {   // Bs stride 128 halfs
    int chunk = col >> 3;
    int sw = (chunk & 8) | ((chunk ^ row) & 7);
    return row * 128 + sw * 8 + (col & 7);
}

__global__ void __launch_bounds__(256) k_gemm2() {
    __shared__ __half As[128 * 64];
    __shared__ __half Bs[32 * 128];
    int tid = threadIdx.x;
    int lane = tid & 31, w = tid >> 5;
    int wm = w & 3, wn = w >> 2;
    int m0 = blockIdx.x * 128;

    float acc[2][8][4];
#pragma unroll
    for (int mt = 0; mt < 2; mt++)
#pragma unroll
        for (int nt = 0; nt < 8; nt++)
#pragma unroll
            for (int q = 0; q < 4; q++) acc[mt][nt][q] = 0.f;

    int arow = tid >> 1;
    int ac0 = (tid & 1) * 2;          // chunks {0,1} or {2,3}
    int brow = tid >> 3;
    int bc0 = (tid & 7) * 2;

    for (int k0 = 0; k0 < D1; k0 += 32) {
        // load A tile (128x32 halfs)
        int grow = m0 + arow;
#pragma unroll
        for (int c = 0; c < 2; c++) {
            int ch = ac0 + c;
            uint4 v = make_uint4(0, 0, 0, 0);
            if (grow < NN)
                v = *(const uint4*)&g_out1[(size_t)grow * D1 + k0 + ch * 8];
            *(uint4*)&As[aswz(arow, ch * 8)] = v;
        }
        // load B tile (32x128 halfs)
#pragma unroll
        for (int c = 0; c < 2; c++) {
            int ch = bc0 + c;
            uint4 v = *(const uint4*)&g_W2h[(size_t)(k0 + brow) * HID + ch * 8];
            *(uint4*)&Bs[bswz(brow, ch * 8)] = v;
        }
        __syncthreads();

#pragma unroll
        for (int kk = 0; kk < 32; kk += 16) {
            unsigned a[2][4];
#pragma unroll
            for (int mt = 0; mt < 2; mt++) {
                int r = wm * 32 + mt * 16 + (lane & 15);
                int cc = kk + (lane >> 4) * 8;
                unsigned addr = (unsigned)__cvta_generic_to_shared(&As[aswz(r, cc)]);
                asm volatile("ldmatrix.sync.aligned.m8n8.x4.shared.b16 {%0,%1,%2,%3}, [%4];"
                             : "=r"(a[mt][0]), "=r"(a[mt][1]), "=r"(a[mt][2]), "=r"(a[mt][3])
                             : "r"(addr));
            }
            unsigned b[8][2];
#pragma unroll
            for (int nt = 0; nt < 8; nt++) {
                int r = kk + (lane & 15);
                int cc = wn * 64 + nt * 8;
                unsigned addr = (unsigned)__cvta_generic_to_shared(&Bs[bswz(r, cc)]);
                asm volatile("ldmatrix.sync.aligned.m8n8.x2.trans.shared.b16 {%0,%1}, [%2];"
                             : "=r"(b[nt][0]), "=r"(b[nt][1]) : "r"(addr));
            }
#pragma unroll
            for (int mt = 0; mt < 2; mt++)
#pragma unroll
                for (int nt = 0; nt < 8; nt++) {
                    asm volatile(
                        "mma.sync.aligned.m16n8k16.row.col.f32.f16.f16.f32 "
                        "{%0,%1,%2,%3}, {%4,%5,%6,%7}, {%8,%9}, {%0,%1,%2,%3};"
                        : "+f"(acc[mt][nt][0]), "+f"(acc[mt][nt][1]),
                          "+f"(acc[mt][nt][2]), "+f"(acc[mt][nt][3])
                        : "r"(a[mt][0]), "r"(a[mt][1]), "r"(a[mt][2]), "r"(a[mt][3]),
                          "r"(b[nt][0]), "r"(b[nt][1]));
                }
        }
        __syncthreads();
    }

    // epilogue: write fp16 h2
#pragma unroll
    for (int mt = 0; mt < 2; mt++) {
        int rbase = m0 + wm * 32 + mt * 16 + (lane >> 2);
#pragma unroll
        for (int nt = 0; nt < 8; nt++) {
            int col = wn * 64 + nt * 8 + (lane & 3) * 2;
            if (rbase < NN) {
                __half2 v = __floats2half2_rn(acc[mt][nt][0], acc[mt][nt][1]);
                *(__half2*)&g_h2[(size_t)rbase * HID + col] = v;
            }
            if (rbase + 8 < NN) {
                __half2 v = __floats2half2_rn(acc[mt][nt][2], acc[mt][nt][3]);
                *(__half2*)&g_h2[(size_t)(rbase + 8) * HID + col] = v;
            }
        }
    }
}

// ---------------- GAT2 attention logits ----------------
__global__ void __launch_bounds__(128) k_al2(const float* __restrict__ as2,
                                             const float* __restrict__ ad2) {
    int n = blockIdx.x, tid = threadIdx.x;
    float v = __half2float(g_h2[(size_t)n * HID + tid]);
    float ps = v * as2[tid], pd = v * ad2[tid];
    __shared__ float sh[8];
    int lane = tid & 31, w = tid >> 5;
    for (int o = 16; o; o >>= 1) {
        ps += __shfl_down_sync(0xffffffffu, ps, o);
        pd += __shfl_down_sync(0xffffffffu, pd, o);
    }
    if (lane == 0) { sh[w] = ps; sh[4 + w] = pd; }
    __syncthreads();
    if (tid == 0) g_als2[n] = sh[0] + sh[1] + sh[2] + sh[3];
    if (tid == 1) g_ald2[n] = sh[4] + sh[5] + sh[6] + sh[7];
}

// ---------------- GAT2: softmax + aggregation ----------------
__global__ void __launch_bounds__(128) k_gat2_agg(const float* __restrict__ b2) {
    int n = blockIdx.x, tid = threadIdx.x;
    int start = g_rowptr[n], end = g_rowptr[n + 1];
    int deg = end - start + 1;
    float aldn = g_ald2[n];
    __shared__ float sm[128];
    __shared__ float s_stat[2];
    __shared__ float s_alpha[128];
    __shared__ int s_src[128];

    float mx = -1e30f;
    for (int i = tid; i < deg; i += 128) {
        int s = (i < deg - 1) ? g_col[start + i] : n;
        float l = g_als2[s] + aldn;
        l = (l > 0.f) ? l : 0.2f * l;
        mx = fmaxf(mx, l);
    }
    sm[tid] = mx;
    __syncthreads();
    for (int st = 64; st > 0; st >>= 1) {
        if (tid < st) sm[tid] = fmaxf(sm[tid], sm[tid + st]);
        __syncthreads();
    }
    if (tid == 0) s_stat[0] = sm[0];
    __syncthreads();
    float m = s_stat[0];

    float sum = 0.f;
    for (int i = tid; i < deg; i += 128) {
        int s = (i < deg - 1) ? g_col[start + i] : n;
        float l = g_als2[s] + aldn;
        l = (l > 0.f) ? l : 0.2f * l;
        sum += __expf(l - m);
    }
    __syncthreads();
    sm[tid] = sum;
    __syncthreads();
    for (int st = 64; st > 0; st >>= 1) {
        if (tid < st) sm[tid] += sm[tid + st];
        __syncthreads();
    }
    if (tid == 0) s_stat[1] = 1.f / (sm[0] + 1e-16f);
    __syncthreads();
    float inv = s_stat[1];

    float acc = 0.f;
    for (int base = 0; base < deg; base += 128) {
        int cnt = min(128, deg - base);
        __syncthreads();
        if (tid < cnt) {
            int i = base + tid;
            int s = (i < deg - 1) ? g_col[start + i] : n;
            float l = g_als2[s] + aldn;
            l = (l > 0.f) ? l : 0.2f * l;
            s_alpha[tid] = __expf(l - m) * inv;
            s_src[tid] = s;
        }
        __syncthreads();
        for (int ii = 0; ii < cnt; ii++)
            acc += s_alpha[ii] * __half2float(g_h2[(size_t)s_src[ii] * HID + tid]);
    }
    float v = acc + b2[tid];
    g_out2[(size_t)n * HID + tid] = (v > 0.f) ? v : 0.f;
}

// ---------------- deterministic mean pool over nodes ----------------
__global__ void __launch_bounds__(128) k_pool_a() {
    int c = threadIdx.x, b = blockIdx.x;
    int n0 = b * PCH, n1 = min(n0 + PCH, NN);
    float s = 0.f;
    for (int n = n0; n < n1; n++) s += g_out2[(size_t)n * HID + c];
    g_partial[b * HID + c] = s;
}

__global__ void __launch_bounds__(128) k_pool_b(int t) {
    int c = threadIdx.x;
    float s = 0.f;
    for (int b = 0; b < PBLK; b++) s += g_partial[b * HID + c];
    g_emb[t * HID + c] = s * (1.0f / NN);
}

// ---------------- GRU + output head ----------------
__global__ void __launch_bounds__(128) k_gru(
    const float* __restrict__ wih, const float* __restrict__ whh,
    const float* __restrict__ bih, const float* __restrict__ bhh,
    const float* __restrict__ wout, const float* __restrict__ bout,
    float* __restrict__ out) {
    int tid = threadIdx.x;
    __shared__ float h[HID], xt[HID];
    __shared__ float red[4];
    h[tid] = 0.f;
    __syncthreads();
    for (int t = 0; t < TT; t++) {
        xt[tid] = g_emb[t * HID + tid];
        __syncthreads();
        float gi[3], gh[3];
#pragma unroll
        for (int q = 0; q < 3; q++) {
            int r = q * HID + tid;
            float s1 = bih[r], s2 = bhh[r];
            const float* wi = &wih[(size_t)r * HID];
            const float* wh = &whh[(size_t)r * HID];
            for (int c = 0; c < HID; c++) {
                s1 += xt[c] * wi[c];
                s2 += h[c] * wh[c];
            }
            gi[q] = s1;
            gh[q] = s2;
        }
        float r  = 1.f / (1.f + __expf(-(gi[0] + gh[0])));
        float z  = 1.f / (1.f + __expf(-(gi[1] + gh[1])));
        float nn = tanhf(gi[2] + r * gh[2]);
        float hn = (1.f - z) * nn + z * h[tid];
        __syncthreads();
        h[tid] = hn;
        __syncthreads();
        float v = hn * wout[tid];
        int lane = tid & 31, w = tid >> 5;
        for (int o = 16; o; o >>= 1) v += __shfl_down_sync(0xffffffffu, v, o);
        if (lane == 0) red[w] = v;
        __syncthreads();
        if (tid == 0) out[t] = red[0] + red[1] + red[2] + red[3] + bout[0];
        __syncthreads();
    }
}

// ---------------- launch ----------------
extern "C" void kernel_launch(void* const* d_in, const int* in_sizes, int n_in,
                              void* d_out, int out_size) {
    const float* x    = (const float*)d_in[0];
    const void*  ei   = d_in[1];
    const float* W1   = (const float*)d_in[2];
    const float* as1  = (const float*)d_in[3];
    const float* ad1  = (const float*)d_in[4];
    const float* b1   = (const float*)d_in[5];
    const float* W2   = (const float*)d_in[6];
    const float* as2  = (const float*)d_in[7];
    const float* ad2  = (const float*)d_in[8];
    const float* b2   = (const float*)d_in[9];
    const float* wih  = (const float*)d_in[10];
    const float* whh  = (const float*)d_in[11];
    const float* bih  = (const float*)d_in[12];
    const float* bhh  = (const float*)d_in[13];
    const float* wout = (const float*)d_in[14];
    const float* bout = (const float*)d_in[15];
    float* out = (float*)d_out;

    k_init<<<(NN + 255) / 256, 256>>>(ei);
    k_count<<<(EE + 255) / 256, 256>>>(ei);
    k_scan<<<1, 1024>>>();
    k_fill<<<(EE + 255) / 256, 256>>>(ei);
    k_w2h<<<(D1 * HID + 255) / 256, 256>>>(W2);

    for (int t = 0; t < TT; t++) {
        k_gat1_lin<<<(NN + 63) / 64, 128>>>(x + (size_t)t * NN * FIN, W1, as1, ad1);
        k_gat1_agg<<<NN, 128>>>(b1);
        k_gemm2<<<(NN + 127) / 128, 256>>>();
        k_al2<<<NN, 128>>>(as2, ad2);
        k_gat2_agg<<<NN, 128>>>(b2);
        k_pool_a<<<PBLK, 128>>>();
        k_pool_b<<<1, 128>>>(t);
    }
    k_gru<<<1, 128>>>(wih, whh, bih, bhh, wout, bout, out);
}